// round 13
// baseline (speedup 1.0000x reference)
#include <cuda_runtime.h>
#include <cuda_fp16.h>
#include <cstdint>

// ---------------------------------------------------------------------------
// GAT layer (sm_100 base target — legacy mma.sync only):
//   k1: H = X @ W                      (tf32 mma.sync m16n8k8, 27us)
//   k2: as/an row dots (fp32); emit g_h16 = fp16 H in k-paired layout
//   k3: Out = elu( (P @ H) / rowsum(P) )  via fp16 mma.sync m16n8k16
//       fp16 tile acc -> fp32 masters. 32x256 per CTA, JT=64, grid 256,
//       2 CTAs/SM. M/adj/an staged via cp.async smem (full-span latency
//       hiding); computeP after group-wait reads smem.
// ---------------------------------------------------------------------------

#define NROWS 8192
#define IND   512
#define OUTD  256
#define JT    64
#define NTILE (NROWS / JT)     // 128

__device__ __align__(16) float  g_h  [NROWS * OUTD];
__device__ __align__(16) __half g_h16[NROWS * OUTD];   // word[jpair*256+n] = {h[2j][n], h[2j+1][n]}
__device__ __align__(16) float  g_as [NROWS];
__device__ __align__(16) float  g_an [NROWS];

#define PSCALE 0.015625f   // 2^-6

// ---------------------------------------------------------------------------
__device__ __forceinline__ float to_tf32(float x) {
    unsigned r;
    asm("cvt.rna.tf32.f32 %0, %1;\n" : "=r"(r) : "f"(x));
    return __uint_as_float(r);
}
__device__ __forceinline__ void mma_tf32(float* d, const unsigned* a,
                                         unsigned b0, unsigned b1) {
    asm volatile(
        "mma.sync.aligned.m16n8k8.row.col.f32.tf32.tf32.f32 "
        "{%0,%1,%2,%3}, {%4,%5,%6,%7}, {%8,%9}, {%0,%1,%2,%3};\n"
        : "+f"(d[0]), "+f"(d[1]), "+f"(d[2]), "+f"(d[3])
        : "r"(a[0]), "r"(a[1]), "r"(a[2]), "r"(a[3]), "r"(b0), "r"(b1));
}
__device__ __forceinline__ void mma_f16a(unsigned* d, const unsigned* a,
                                         unsigned b0, unsigned b1) {
    asm volatile(
        "mma.sync.aligned.m16n8k16.row.col.f16.f16.f16.f16 "
        "{%0,%1}, {%2,%3,%4,%5}, {%6,%7}, {%0,%1};\n"
        : "+r"(d[0]), "+r"(d[1])
        : "r"(a[0]), "r"(a[1]), "r"(a[2]), "r"(a[3]), "r"(b0), "r"(b1));
}
__device__ __forceinline__ void ldsm4(unsigned* a, unsigned addr) {
    asm volatile(
        "ldmatrix.sync.aligned.m8n8.x4.shared.b16 {%0,%1,%2,%3}, [%4];\n"
        : "=r"(a[0]), "=r"(a[1]), "=r"(a[2]), "=r"(a[3]) : "r"(addr));
}
__device__ __forceinline__ void cp16(void* smem, const void* g) {
    unsigned s = (unsigned)__cvta_generic_to_shared(smem);
    asm volatile("cp.async.cg.shared.global [%0], [%1], 16;\n" :: "r"(s), "l"(g));
}
__device__ __forceinline__ float elu_f(float x) { return x > 0.f ? x : expm1f(x); }

// ---------------------------------------------------------------------------
// Kernel 1: H = X @ W, tf32 mma.sync (R6-proven, 27us). grid (2, 64).
// ---------------------------------------------------------------------------
#define K1_SMEM_BYTES ((2 * 128 * 36 + 2 * 32 * 136) * 4)

__global__ __launch_bounds__(256) void k1_gemm_xw(const float* __restrict__ X,
                                                  const float* __restrict__ W) {
    extern __shared__ float sm1[];
    float* sX = sm1;
    float* sW = sm1 + 2 * 128 * 36;

    const int tid = threadIdx.x;
    const int lane = tid & 31, warp = tid >> 5;
    const int wr = warp & 3, wc = warp >> 2;
    const int m0 = blockIdx.y * 128, n0 = blockIdx.x * 128;
    const int r0 = lane >> 2, c0 = lane & 3;
    const int sel = lane >> 3, mrow = lane & 7;
    const int lrow = ((sel & 1) << 3) + mrow, lcol = (sel >> 1) << 2;
    const unsigned sX_u = (unsigned)__cvta_generic_to_shared(sX);

    float acc[2][8][4] = {};
    float4 xv[4], wv[4];

    auto ldg_stage = [&](int k0) {
#pragma unroll
        for (int p = 0; p < 4; p++) {
            int q = tid + p * 256;
            xv[p] = *(const float4*)&X[(size_t)(m0 + (q >> 3)) * IND + k0 + ((q & 7) << 2)];
            wv[p] = *(const float4*)&W[(size_t)(k0 + (q >> 5)) * OUTD + n0 + ((q & 31) << 2)];
        }
    };
    auto sts_stage = [&](int buf) {
#pragma unroll
        for (int p = 0; p < 4; p++) {
            int q = tid + p * 256;
            float4 t = make_float4(to_tf32(xv[p].x), to_tf32(xv[p].y),
                                   to_tf32(xv[p].z), to_tf32(xv[p].w));
            *(float4*)&sX[buf * 4608 + (q >> 3) * 36 + ((q & 7) << 2)] = t;
            float4 u = make_float4(to_tf32(wv[p].x), to_tf32(wv[p].y),
                                   to_tf32(wv[p].z), to_tf32(wv[p].w));
            *(float4*)&sW[buf * 4352 + (q >> 5) * 136 + ((q & 31) << 2)] = u;
        }
    };

    ldg_stage(0);
    sts_stage(0);
    __syncthreads();

    for (int s = 0; s < 16; s++) {
        const int buf = s & 1;
        if (s < 15) ldg_stage((s + 1) * 32);
#pragma unroll
        for (int k8 = 0; k8 < 4; k8++) {
            const int kb = k8 << 3;
            unsigned afr[2][4];
#pragma unroll
            for (int mt = 0; mt < 2; mt++) {
                unsigned addr = sX_u +
                    (buf * 4608 + (wr * 32 + mt * 16 + lrow) * 36 + kb + lcol) * 4u;
                ldsm4(afr[mt], addr);
            }
            const float* wp = &sW[buf * 4352 + (kb + c0) * 136 + wc * 64 + r0];
#pragma unroll
            for (int nt = 0; nt < 8; nt++) {
                unsigned b0 = __float_as_uint(wp[nt * 8]);
                unsigned b1 = __float_as_uint(wp[4 * 136 + nt * 8]);
#pragma unroll
                for (int mt = 0; mt < 2; mt++)
                    mma_tf32(acc[mt][nt], afr[mt], b0, b1);
            }
        }
        if (s < 15) {
            __syncthreads();
            sts_stage((s + 1) & 1);
            __syncthreads();
        }
    }
#pragma unroll
    for (int mt = 0; mt < 2; mt++)
#pragma unroll
        for (int nt = 0; nt < 8; nt++) {
            const int ra = wr * 32 + mt * 16 + r0;
            const int cb = wc * 64 + nt * 8 + c0 * 2;
            *(float2*)&g_h[(size_t)(m0 + ra) * OUTD + n0 + cb] =
                make_float2(acc[mt][nt][0], acc[mt][nt][1]);
            *(float2*)&g_h[(size_t)(m0 + ra + 8) * OUTD + n0 + cb] =
                make_float2(acc[mt][nt][2], acc[mt][nt][3]);
        }
}

// ---------------------------------------------------------------------------
// Kernel 2: as/an row dots (fp32); write g_h16 (fp16, k-paired layout).
// ---------------------------------------------------------------------------
__global__ __launch_bounds__(256) void k2_attvec(const float* __restrict__ a_self,
                                                 const float* __restrict__ a_neighs) {
    const int warp = threadIdx.x >> 5, lane = threadIdx.x & 31;
    const int row = blockIdx.x * 8 + warp;
    const float4* h4 = (const float4*)&g_h[(size_t)row * OUTD];
    __half* dst = &g_h16[(size_t)(row >> 1) * 512 + (row & 1)];
    float s1 = 0.f, s2 = 0.f;
#pragma unroll
    for (int q = 0; q < 2; q++) {
        float4 v = h4[lane + 32 * q];
        float4 a = ((const float4*)a_self)[lane + 32 * q];
        float4 b = ((const float4*)a_neighs)[lane + 32 * q];
        s1 += v.x * a.x + v.y * a.y + v.z * a.z + v.w * a.w;
        s2 += v.x * b.x + v.y * b.y + v.z * b.z + v.w * b.w;
        const int c = (lane + 32 * q) * 4;
        dst[(c + 0) * 2] = __float2half_rn(v.x);
        dst[(c + 1) * 2] = __float2half_rn(v.y);
        dst[(c + 2) * 2] = __float2half_rn(v.z);
        dst[(c + 3) * 2] = __float2half_rn(v.w);
    }
#pragma unroll
    for (int off = 16; off >= 1; off >>= 1) {
        s1 += __shfl_xor_sync(0xffffffffu, s1, off);
        s2 += __shfl_xor_sync(0xffffffffu, s2, off);
    }
    if (lane == 0) { g_as[row] = s1; g_an[row] = s2; }
}

// ---------------------------------------------------------------------------
// Kernel 3: fused masked-exp attention GEMM, fp16 m16n8k16 fp16-acc.
// 32 rows x 256 cols per CTA, 128 k-tiles of 64 j. grid 256, 256 thr.
// All inputs staged via cp.async double buffers: H, M, adj, an.
// smem = 111360 B -> 2 CTAs/SM.
// ---------------------------------------------------------------------------
#define SHU_STRIDE 260
#define SHU_BUF    (32 * SHU_STRIDE)          // 8320 u32 per buffer
#define SMA_STRIDE 68                         // floats per M/adj row
#define SMA_BUF    (32 * SMA_STRIDE)          // 2176 floats per buffer
#define SM_F       (2 * SHU_BUF)              // float idx 16640
#define SA_F       (SM_F + 2 * SMA_BUF)       // 20992
#define SP_BYTE0   ((SA_F + 2 * SMA_BUF) * 4) // byte 101376
#define SP_STRIDE  72                         // halves per row
#define SP_HBUF    (32 * SP_STRIDE)           // 2304 halves per buffer
#define SAS_F      ((SP_BYTE0 + 2 * SP_HBUF * 2) / 4)  // 27648
#define SRS_F      (SAS_F + 32)               // 27680
#define SAN_F      (SRS_F + 32)               // 27712
#define K3_SMEM_BYTES ((SAN_F + 128) * 4)     // 111360

__global__ __launch_bounds__(256, 2) void k3_attn(const float* __restrict__ Adj,
                                                  const float* __restrict__ Mg,
                                                  float* __restrict__ Out) {
    extern __shared__ float sm[];
    uint32_t* sHu = (uint32_t*)sm;
    float*    sM  = sm + SM_F;
    float*    sA  = sm + SA_F;
    __half*   sPh = (__half*)((char*)sm + SP_BYTE0);
    float* s_as = sm + SAS_F;
    float* s_rs = sm + SRS_F;
    float* s_an = sm + SAN_F;

    const int tid = threadIdx.x;
    const int lane = tid & 31, warp = tid >> 5;
    const int rowbase = blockIdx.x * 32;
    const int r0 = lane >> 2, c0 = lane & 3;
    const int g = tid >> 3, cbase = (tid & 7) << 3;   // row g, 8 cols per thread
    const unsigned sP_u = (unsigned)__cvta_generic_to_shared(sPh);

    if (tid < 8)
        *(float4*)&s_as[tid * 4] = *(const float4*)&g_as[rowbase + tid * 4];

    auto stage = [&](int tt) {
        const int b = tt & 1;
        const int jb = tt * JT;
        // H tile: 32 jpair-rows x 1024 B
        const char* src = (const char*)g_h16 + (size_t)tt * 32 * 1024;
#pragma unroll
        for (int p = 0; p < 8; p++) {
            int ch = tid + p * 256;
            int pr = ch >> 6, c = ch & 63;
            cp16(&sHu[b * SHU_BUF + pr * SHU_STRIDE + c * 4],
                 src + (size_t)pr * 1024 + c * 16);
        }
        // M + adj tiles: 32 rows x 64 floats each
#pragma unroll
        for (int p = 0; p < 2; p++) {
            int ch = tid + p * 256;
            int r = ch >> 4, c = (ch & 15) << 2;
            size_t goff = (size_t)(rowbase + r) * NROWS + jb + c;
            cp16(&sM[b * SMA_BUF + r * SMA_STRIDE + c], &Mg[goff]);
            cp16(&sA[b * SMA_BUF + r * SMA_STRIDE + c], &Adj[goff]);
        }
        if (tid < 16)
            cp16(&s_an[b * 64 + tid * 4], &g_an[jb + tid * 4]);
        asm volatile("cp.async.commit_group;\n" ::: "memory");
    };

    float rsum = 0.f;

    auto computeP = [&](int tt) {
        const int b = tt & 1;
        const float asr = s_as[g];
        const float* mp = &sM[b * SMA_BUF + g * SMA_STRIDE + cbase];
        const float* ap = &sA[b * SMA_BUF + g * SMA_STRIDE + cbase];
        float p[8];
#pragma unroll
        for (int hh = 0; hh < 2; hh++) {
            float4 m4 = *(const float4*)(mp + hh * 4);
            float4 a4 = *(const float4*)(ap + hh * 4);
            float4 an = *(const float4*)&s_an[b * 64 + cbase + hh * 4];
            float t0 = (asr + an.x) * m4.x; t0 = t0 > 0.f ? t0 : 0.2f * t0;
            float t1 = (asr + an.y) * m4.y; t1 = t1 > 0.f ? t1 : 0.2f * t1;
            float t2 = (asr + an.z) * m4.z; t2 = t2 > 0.f ? t2 : 0.2f * t2;
            float t3 = (asr + an.w) * m4.w; t3 = t3 > 0.f ? t3 : 0.2f * t3;
            p[hh * 4 + 0] = a4.x > 0.f ? __expf(t0) : 0.f;
            p[hh * 4 + 1] = a4.y > 0.f ? __expf(t1) : 0.f;
            p[hh * 4 + 2] = a4.z > 0.f ? __expf(t2) : 0.f;
            p[hh * 4 + 3] = a4.w > 0.f ? __expf(t3) : 0.f;
        }
        rsum += ((p[0] + p[1]) + (p[2] + p[3])) +
                ((p[4] + p[5]) + (p[6] + p[7]));
        __half2 h01 = __floats2half2_rn(p[0] * PSCALE, p[1] * PSCALE);
        __half2 h23 = __floats2half2_rn(p[2] * PSCALE, p[3] * PSCALE);
        __half2 h45 = __floats2half2_rn(p[4] * PSCALE, p[5] * PSCALE);
        __half2 h67 = __floats2half2_rn(p[6] * PSCALE, p[7] * PSCALE);
        *(uint4*)&sPh[b * SP_HBUF + g * SP_STRIDE + cbase] =
            make_uint4(*(unsigned*)&h01, *(unsigned*)&h23,
                       *(unsigned*)&h45, *(unsigned*)&h67);
    };

    float acc[2][4][4] = {};   // fp32 masters

    // ---- prologue ----
    stage(0);
    asm volatile("cp.async.wait_group 0;\n" ::: "memory");
    __syncthreads();
    computeP(0);
    __syncthreads();

    // ---- main loop: 128 iterations ----
    for (int t = 0; t < NTILE; t++) {
        const int b = t & 1;
        const bool more = (t < NTILE - 1);
        if (more) stage(t + 1);

        unsigned hacc[2][4][2] = {};
        {
            const int nb = warp * 32 + r0;
#pragma unroll
            for (int c16 = 0; c16 < 4; c16++) {
                unsigned afr[2][4];
#pragma unroll
                for (int mt = 0; mt < 2; mt++) {
                    unsigned addr = sP_u +
                        (b * SP_HBUF + (mt * 16 + (lane & 15)) * SP_STRIDE +
                         c16 * 16 + (lane >> 4) * 8) * 2u;
                    ldsm4(afr[mt], addr);
                }
                const uint32_t* hp =
                    &sHu[b * SHU_BUF + (c16 * 8 + c0) * SHU_STRIDE + nb];
#pragma unroll
                for (int nt = 0; nt < 4; nt++) {
                    unsigned b0 = hp[nt * 8];
                    unsigned b1 = hp[4 * SHU_STRIDE + nt * 8];
#pragma unroll
                    for (int mt = 0; mt < 2; mt++)
                        mma_f16a(hacc[mt][nt], afr[mt], b0, b1);
                }
            }
        }

        // promote fp16 tile accumulators into fp32 masters
#pragma unroll
        for (int mt = 0; mt < 2; mt++)
#pragma unroll
            for (int nt = 0; nt < 4; nt++) {
                float2 lo = __half22float2(*(__half2*)&hacc[mt][nt][0]);
                float2 hi = __half22float2(*(__half2*)&hacc[mt][nt][1]);
                acc[mt][nt][0] += lo.x; acc[mt][nt][1] += lo.y;
                acc[mt][nt][2] += hi.x; acc[mt][nt][3] += hi.y;
            }

        if (more) {
            asm volatile("cp.async.wait_group 0;\n" ::: "memory");
            __syncthreads();          // mma(t) done everywhere; stage(t+1) visible
            computeP(t + 1);          // smem reads, writes sPh[(t+1)&1]
        }
        __syncthreads();              // P(t+1) visible for next iter
    }

    // ---- rowsum reduction (8 threads per row, same warp) ----
#pragma unroll
    for (int off = 4; off >= 1; off >>= 1)
        rsum += __shfl_xor_sync(0xffffffffu, rsum, off);
    if ((tid & 7) == 0) s_rs[g] = rsum;
    __syncthreads();

    // ---- epilogue: divide (undo 2^-6 scale), elu, store ----
#pragma unroll
    for (int mt = 0; mt < 2; mt++) {
        const int ra = mt * 16 + r0;
        const float ia = 64.0f / s_rs[ra];
        const float ib = 64.0f / s_rs[ra + 8];
#pragma unroll
        for (int nt = 0; nt < 4; nt++) {
            const int col = warp * 32 + nt * 8 + c0 * 2;
            float2 va = make_float2(elu_f(acc[mt][nt][0] * ia),
                                    elu_f(acc[mt][nt][1] * ia));
            float2 vb = make_float2(elu_f(acc[mt][nt][2] * ib),
                                    elu_f(acc[mt][nt][3] * ib));
            *(float2*)&Out[(size_t)(rowbase + ra) * OUTD + col] = va;
            *(float2*)&Out[(size_t)(rowbase + ra + 8) * OUTD + col] = vb;
        }
    }
}

// ---------------------------------------------------------------------------
extern "C" void kernel_launch(void* const* d_in, const int* in_sizes, int n_in,
                              void* d_out, int out_size) {
    const float* X        = (const float*)d_in[0];
    const float* Adj      = (const float*)d_in[1];
    const float* Mg       = (const float*)d_in[2];
    const float* W        = (const float*)d_in[3];
    const float* a_self   = (const float*)d_in[4];
    const float* a_neighs = (const float*)d_in[5];
    float* Out = (float*)d_out;

    cudaFuncSetAttribute(k1_gemm_xw, cudaFuncAttributeMaxDynamicSharedMemorySize,
                         K1_SMEM_BYTES);
    cudaFuncSetAttribute(k3_attn, cudaFuncAttributeMaxDynamicSharedMemorySize,
                         K3_SMEM_BYTES);

    k1_gemm_xw<<<dim3(2, 64), 256, K1_SMEM_BYTES>>>(X, W);
    k2_attvec<<<1024, 256>>>(a_self, a_neighs);
    k3_attn<<<256, 256, K3_SMEM_BYTES>>>(Adj, Mg, Out);
}